// round 1
// baseline (speedup 1.0000x reference)
#include <cuda_runtime.h>

// CIN (cross-interaction network), 3 layers.
// out[r, j] = sum_{h,m} xl[r,h] * x0[r,m] * W[h*32+m, j]  (+bias, relu for layers 0,1)
// r = b*16 + d, x0[r, m] = inputs[b*512 + m*16 + d]
// Final output: out[b, L*128 + j] = sum_{d=0..15} xl_next[b*16+d, j]

namespace {
constexpr int BATCH = 1024;
constexpr int DD    = 16;           // embedding dim (reduced at the end)
constexpr int MF    = 32;           // num_feat
constexpr int RTOT  = BATCH * DD;   // 16384 rows
constexpr int NOUT  = 128;          // hidden units per layer
constexpr int TM    = 64;           // rows per block (= 4 batches)
constexpr int NTHR  = 256;
constexpr int OUTW  = 3 * NOUT;     // 384 output cols
}

// Intermediate xl buffers (allocation-free rule: device globals)
__device__ __align__(16) float g_xl1[RTOT * NOUT];
__device__ __align__(16) float g_xl2[RTOT * NOUT];

template <int LAYER>
__global__ __launch_bounds__(NTHR, 2)
void cin_layer(const float* __restrict__ inputs,
               const float* __restrict__ W,
               const float* __restrict__ bias,
               float* __restrict__ out)
{
    constexpr int  H        = (LAYER == 0) ? MF : NOUT;  // xl width this layer
    constexpr bool RELU     = (LAYER < 2);
    constexpr bool WRITE_XL = (LAYER < 2);

    __shared__ float x0s[TM][MF + 1];                    // padded: conflict-free row reads
    __shared__ __align__(16) float Ws[MF][NOUT];         // one h-chunk of W (32x128)
    __shared__ float psum[16][NOUT];                     // per-(4-row-group) partial sums

    const int tid = threadIdx.x;
    const int tx  = tid & 15;   // col group: cols tx*8 .. tx*8+7
    const int ty  = tid >> 4;   // row group: rows ty*4 .. ty*4+3
    const int blk = blockIdx.x;
    const int R0  = blk * TM;

    // ---- load x0 tile: 4 batches => contiguous 2048 floats of `inputs` ----
    {
        const float* src = inputs + blk * 2048;
        #pragma unroll
        for (int k = 0; k < 2048 / NTHR; k++) {
            int i  = tid + k * NTHR;
            int bb = i >> 9;          // local batch 0..3
            int m  = (i >> 4) & 31;   // feature
            int d  = i & 15;          // embedding
            x0s[bb * 16 + d][m] = src[i];
        }
    }

    const float* xl_in  = (LAYER == 2) ? g_xl2 : g_xl1;  // unused for LAYER==0
    float*       xl_out = (LAYER == 0) ? g_xl1 : g_xl2;

    float acc[4][8];
    #pragma unroll
    for (int i = 0; i < 4; i++)
        #pragma unroll
        for (int j = 0; j < 8; j++) acc[i][j] = 0.f;

    // ---- W chunk register double-buffer; prologue: chunk h=0 ----
    float4 wreg[4];
    #pragma unroll
    for (int k = 0; k < 4; k++)
        wreg[k] = reinterpret_cast<const float4*>(W)[tid + NTHR * k];
    #pragma unroll
    for (int k = 0; k < 4; k++)
        reinterpret_cast<float4*>(&Ws[0][0])[tid + NTHR * k] = wreg[k];
    __syncthreads();  // also covers x0s visibility

    // ---- main K loop: h outer (W chunk = rows h*32..h*32+31), m inner ----
    for (int h = 0; h < H; h++) {
        if (h + 1 < H) {  // prefetch next W chunk into registers
            const float4* src =
                reinterpret_cast<const float4*>(W + (h + 1) * (MF * NOUT));
            #pragma unroll
            for (int k = 0; k < 4; k++) wreg[k] = src[tid + NTHR * k];
        }

        float xlh[4];
        #pragma unroll
        for (int i = 0; i < 4; i++) {
            if (LAYER == 0)
                xlh[i] = x0s[ty * 4 + i][h];            // layer 0: xl == x0
            else
                xlh[i] = __ldg(&xl_in[(R0 + ty * 4 + i) * NOUT + h]);
        }

        #pragma unroll 8
        for (int m = 0; m < MF; m++) {
            float4 w0 = *reinterpret_cast<const float4*>(&Ws[m][tx * 8]);
            float4 w1 = *reinterpret_cast<const float4*>(&Ws[m][tx * 8 + 4]);
            float z[4];
            #pragma unroll
            for (int i = 0; i < 4; i++) z[i] = xlh[i] * x0s[ty * 4 + i][m];
            #pragma unroll
            for (int i = 0; i < 4; i++) {
                acc[i][0] += z[i] * w0.x;
                acc[i][1] += z[i] * w0.y;
                acc[i][2] += z[i] * w0.z;
                acc[i][3] += z[i] * w0.w;
                acc[i][4] += z[i] * w1.x;
                acc[i][5] += z[i] * w1.y;
                acc[i][6] += z[i] * w1.z;
                acc[i][7] += z[i] * w1.w;
            }
        }

        if (h + 1 < H) {
            __syncthreads();  // everyone done reading current Ws
            #pragma unroll
            for (int k = 0; k < 4; k++)
                reinterpret_cast<float4*>(&Ws[0][0])[tid + NTHR * k] = wreg[k];
            __syncthreads();  // next Ws visible
        }
    }

    // ---- epilogue: bias (+relu), store xl, per-batch d-reduction ----
    float bv[8];
    #pragma unroll
    for (int j = 0; j < 8; j++) bv[j] = __ldg(&bias[tx * 8 + j]);

    float rs[8];
    #pragma unroll
    for (int j = 0; j < 8; j++) rs[j] = 0.f;

    #pragma unroll
    for (int i = 0; i < 4; i++) {
        float v[8];
        #pragma unroll
        for (int j = 0; j < 8; j++) {
            float t = acc[i][j] + bv[j];
            if (RELU) t = fmaxf(t, 0.f);
            v[j] = t;
            rs[j] += t;
        }
        if (WRITE_XL) {
            float4* dst = reinterpret_cast<float4*>(
                &xl_out[(R0 + ty * 4 + i) * NOUT + tx * 8]);
            dst[0] = make_float4(v[0], v[1], v[2], v[3]);
            dst[1] = make_float4(v[4], v[5], v[6], v[7]);
        }
    }

    #pragma unroll
    for (int j = 0; j < 8; j++) psum[ty][tx * 8 + j] = rs[j];
    __syncthreads();

    // rows ty*4..ty*4+3 belong to local batch ty/4; combine 4 ty-groups per batch
    for (int o = tid; o < 4 * NOUT; o += NTHR) {
        int bl = o >> 7;
        int c  = o & 127;
        float s = psum[bl * 4 + 0][c] + psum[bl * 4 + 1][c] +
                  psum[bl * 4 + 2][c] + psum[bl * 4 + 3][c];
        out[(blk * 4 + bl) * OUTW + LAYER * NOUT + c] = s;
    }
}

extern "C" void kernel_launch(void* const* d_in, const int* in_sizes, int n_in,
                              void* d_out, int out_size)
{
    const float* inputs = (const float*)d_in[0];
    const float* W0     = (const float*)d_in[1];
    const float* b0     = (const float*)d_in[2];
    const float* W1     = (const float*)d_in[3];
    const float* b1     = (const float*)d_in[4];
    const float* W2     = (const float*)d_in[5];
    const float* b2     = (const float*)d_in[6];
    float* out = (float*)d_out;

    dim3 grid(RTOT / TM);   // 256 blocks
    dim3 block(NTHR);
    cin_layer<0><<<grid, block>>>(inputs, W0, b0, out);
    cin_layer<1><<<grid, block>>>(inputs, W1, b1, out);
    cin_layer<2><<<grid, block>>>(inputs, W2, b2, out);
}

// round 4
// speedup vs baseline: 9.8876x; 9.8876x over previous
#include <cuda_runtime.h>
#include <cuda_fp16.h>
#include <cstdint>

// CIN via legacy tensor cores (mma.sync, base ISA — tcgen05 unavailable on
// this harness's plain sm_103 ptxas target).
// out[r,j] = sum_{h,m} xl[r,h]*x0[r,m]*W[h*32+m,j]; r = b*16+d.
// A (=Z) generated on the fly in fp16 SMEM, B = W^T fp16 via cp.async.

namespace {
constexpr int RTOT = 16384;           // 1024 batches * 16 emb rows
constexpr int NOUT = 128;
constexpr int OUTW = 384;
constexpr int TM   = 128;             // rows per CTA
constexpr int NCTA = RTOT / TM;       // 128
constexpr int NTHR = 256;

// SMEM layout (bytes)
constexpr int OFF_A    = 0;           // 2 stages x 16384 (128 rows x 64 halves)
constexpr int OFF_B    = 32768;       // 2 stages x 16384 (128 n    x 64 halves)
constexpr int OFF_X0   = 65536;       // float[128][33]
constexpr int OFF_BIAS = OFF_X0 + 128 * 33 * 4;   // 82432
constexpr int SMEM_TOTAL = OFF_BIAS + 512;        // 82944
}

// device-global scratch (allocation-free rule)
__device__ __align__(16) __half g_Wt[128 * (1024 + 4096 + 4096)]; // [layer][j][k]
__device__ __align__(16) float  g_xlA[RTOT * NOUT];  // transposed [col][row]
__device__ __align__(16) float  g_xlB[RTOT * NOUT];

// ---------------- helpers ----------------
__device__ __forceinline__ uint32_t smem_u32(const void* p) {
    uint32_t a;
    asm("{ .reg .u64 t; cvta.to.shared.u64 t, %1; cvt.u32.u64 %0, t; }" : "=r"(a) : "l"(p));
    return a;
}
__device__ __forceinline__ void ldsm4(uint32_t* r, uint32_t addr) {
    asm volatile("ldmatrix.sync.aligned.m8n8.x4.shared.b16 {%0,%1,%2,%3}, [%4];"
                 : "=r"(r[0]), "=r"(r[1]), "=r"(r[2]), "=r"(r[3]) : "r"(addr));
}
__device__ __forceinline__ void mma16816(float* c, const uint32_t* a, const uint32_t* b) {
    asm volatile("mma.sync.aligned.m16n8k16.row.col.f32.f16.f16.f32 "
                 "{%0,%1,%2,%3}, {%4,%5,%6,%7}, {%8,%9}, {%0,%1,%2,%3};"
                 : "+f"(c[0]), "+f"(c[1]), "+f"(c[2]), "+f"(c[3])
                 : "r"(a[0]), "r"(a[1]), "r"(a[2]), "r"(a[3]), "r"(b[0]), "r"(b[1]));
}
#define CP_ASYNC16(dst, src) \
    asm volatile("cp.async.cg.shared.global [%0], [%1], 16;" :: "r"(dst), "l"(src) : "memory")
#define CP_COMMIT()  asm volatile("cp.async.commit_group;" ::: "memory")
#define CP_WAIT0()   asm volatile("cp.async.wait_group 0;" ::: "memory")

// ---------------- W transpose + fp16 convert ----------------
template <int LAYER>
__global__ void wprep(const float* __restrict__ W) {
    constexpr int K    = (LAYER == 0) ? 1024 : 4096;
    constexpr int WOFF = (LAYER == 0) ? 0 : (LAYER == 1 ? 131072 : 655360);
    __half* Wt = g_Wt + WOFF;
    __shared__ float s[32][129];
    const int k0 = blockIdx.x * 32;
    const int t  = threadIdx.x;
#pragma unroll
    for (int i = 0; i < 16; i++) {
        int idx = t + i * 256;
        int kk = idx >> 7, j = idx & 127;
        s[kk][j] = W[(size_t)(k0 + kk) * 128 + j];
    }
    __syncthreads();
    const int j = t >> 1, hb = t & 1;
#pragma unroll
    for (int r = 0; r < 2; r++) {
        uint32_t w[4];
#pragma unroll
        for (int e = 0; e < 4; e++) {
            int kk = hb * 16 + r * 8 + e * 2;
            __half2 h2 = __floats2half2_rn(s[kk][j], s[kk + 1][j]);
            w[e] = *reinterpret_cast<uint32_t*>(&h2);
        }
        *reinterpret_cast<uint4*>(Wt + (size_t)j * K + k0 + hb * 16 + r * 8) =
            make_uint4(w[0], w[1], w[2], w[3]);
    }
}

// ---------------- main layer kernel ----------------
template <int LAYER>
__global__ __launch_bounds__(NTHR, 1)
void cin_mma(const float* __restrict__ inputs,
             const float* __restrict__ bias,
             float* __restrict__ out)
{
    constexpr int  K    = (LAYER == 0) ? 1024 : 4096;
    constexpr int  WOFF = (LAYER == 0) ? 0 : (LAYER == 1 ? 131072 : 655360);
    constexpr int  NC   = K / 64;          // 64-wide K chunks
    constexpr bool RELU = (LAYER < 2);
    constexpr bool WXL  = (LAYER < 2);

    extern __shared__ char smem[];
    const uint32_t sb = smem_u32(smem);

    const int tid  = threadIdx.x;
    const int wid  = tid >> 5;
    const int lane = tid & 31;
    const int blk  = blockIdx.x;
    const int R0   = blk * TM;

    const __half* Wt     = g_Wt + WOFF;
    const float*  xl_in  = (LAYER == 2) ? g_xlB : g_xlA;
    float*        xl_out = (LAYER == 0) ? g_xlA : g_xlB;

    // ---- B chunk prefetch (cp.async) into SW128-swizzled [n][k] tile ----
    auto issue_b = [&](int cc) {
        const int s = cc & 1;
        const __half* wsrc = Wt + cc * 64;
        const uint32_t bbase = sb + OFF_B + s * 16384;
#pragma unroll
        for (int i = 0; i < 4; i++) {
            int idx = tid + i * 256;
            int j = idx >> 3, q = idx & 7;
            const __half* g = wsrc + (size_t)j * K + q * 8;
            uint32_t d = bbase + j * 128 + ((q * 16) ^ ((j & 7) << 4));
            CP_ASYNC16(d, g);
        }
        CP_COMMIT();
    };

    issue_b(0);

    // ---- x0 tile + bias -> SMEM ----
    {
        const float* src = inputs + (size_t)blk * 4096;   // 8 batches contiguous
        float* x0sw = reinterpret_cast<float*>(smem + OFF_X0);
#pragma unroll
        for (int i = 0; i < 16; i++) {
            int idx = tid + i * NTHR;
            int bb = idx >> 9, m = (idx >> 4) & 31, d = idx & 15;
            x0sw[(bb * 16 + d) * 33 + m] = src[idx];
        }
        if (tid < 128) reinterpret_cast<float*>(smem + OFF_BIAS)[tid] = bias[tid];
    }
    __syncthreads();

    // ---- per-thread Z-gen setup ----
    const int row  = tid >> 1;      // 0..127
    const int half = tid & 1;       // which 32-k half of the 64 chunk
    const float* x0s = reinterpret_cast<const float*>(smem + OFF_X0);
    float x0r[32];
#pragma unroll
    for (int m = 0; m < 32; m++) x0r[m] = x0s[row * 33 + m];
    const uint32_t xorv = (uint32_t)(row & 7) << 4;
    char* const arow_ptr = smem + OFF_A + row * 128;

    // ---- accumulators ----
    float acc[4][4][4];
#pragma unroll
    for (int mt = 0; mt < 4; mt++)
#pragma unroll
        for (int nt = 0; nt < 4; nt++)
#pragma unroll
            for (int e = 0; e < 4; e++) acc[mt][nt][e] = 0.f;

    const int mrb  = (wid >> 2) * 64;   // warp M base (rows)
    const int ncol = (wid & 3) * 32;    // warp N base (cols)
    const int g    = lane >> 3;         // ldmatrix address group

    // ================= main K loop =================
    for (int c = 0; c < NC; c++) {
        const int s = c & 1;

        // ---- generate Z chunk (fp16) into A[s] ----
        {
            const int h = c * 2 + half;
            float xlv;
            if (LAYER == 0) xlv = x0s[row * 33 + h];
            else            xlv = __ldg(&xl_in[(size_t)h * RTOT + R0 + row]);
            char* base = arow_ptr + s * 16384;
#pragma unroll
            for (int q = 0; q < 4; q++) {
                uint32_t w[4];
#pragma unroll
                for (int e = 0; e < 4; e++) {
                    const int m = q * 8 + e * 2;
                    __half2 h2 = __floats2half2_rn(xlv * x0r[m], xlv * x0r[m + 1]);
                    w[e] = *reinterpret_cast<uint32_t*>(&h2);
                }
                const uint32_t off = (uint32_t)(half * 64 + q * 16) ^ xorv;
                *reinterpret_cast<uint4*>(base + off) = make_uint4(w[0], w[1], w[2], w[3]);
            }
        }

        CP_WAIT0();          // B(c) landed (per-thread)
        __syncthreads();     // A[s] + B[s] visible to all

        if (c + 1 < NC) issue_b(c + 1);   // safe: everyone done reading B[s^1]

        // ---- compute: 4 k16 steps, 16 mma each ----
        const uint32_t abase = sb + OFF_A + s * 16384;
        const uint32_t bbase = sb + OFF_B + s * 16384;
#pragma unroll
        for (int ks = 0; ks < 4; ks++) {
            const int k0 = ks * 16;
            uint32_t afr[4][4];
#pragma unroll
            for (int mt = 0; mt < 4; mt++) {
                const int ar = mrb + mt * 16 + (g & 1) * 8 + (lane & 7);
                const int ak = k0 + (g >> 1) * 8;
                ldsm4(afr[mt], abase + ar * 128 + (((uint32_t)ak * 2) ^ ((ar & 7) << 4)));
            }
            uint32_t bfr[4][2];
#pragma unroll
            for (int bt = 0; bt < 2; bt++) {
                const int br = ncol + bt * 16 + (g >> 1) * 8 + (lane & 7);
                const int bk = k0 + (g & 1) * 8;
                uint32_t r[4];
                ldsm4(r, bbase + br * 128 + (((uint32_t)bk * 2) ^ ((br & 7) << 4)));
                bfr[bt * 2][0] = r[0]; bfr[bt * 2][1] = r[1];
                bfr[bt * 2 + 1][0] = r[2]; bfr[bt * 2 + 1][1] = r[3];
            }
#pragma unroll
            for (int mt = 0; mt < 4; mt++)
#pragma unroll
                for (int nt = 0; nt < 4; nt++)
                    mma16816(acc[mt][nt], afr[mt], bfr[nt]);
        }
    }

    // ================= epilogue =================
    const float* biass = reinterpret_cast<const float*>(smem + OFF_BIAS);
#pragma unroll
    for (int mt = 0; mt < 4; mt++) {
        const int batch = blk * 8 + (wid >> 2) * 4 + mt;   // one m16 tile == one batch
        const int r0 = R0 + mrb + mt * 16 + (lane >> 2);
#pragma unroll
        for (int nt = 0; nt < 4; nt++) {
            const int j0 = ncol + nt * 8 + (lane & 3) * 2;
            const float b0 = biass[j0], b1 = biass[j0 + 1];
            float v0 = acc[mt][nt][0] + b0;
            float v1 = acc[mt][nt][1] + b1;
            float v2 = acc[mt][nt][2] + b0;
            float v3 = acc[mt][nt][3] + b1;
            if (RELU) {
                v0 = fmaxf(v0, 0.f); v1 = fmaxf(v1, 0.f);
                v2 = fmaxf(v2, 0.f); v3 = fmaxf(v3, 0.f);
            }
            if (WXL) {
                xl_out[(size_t)j0 * RTOT + r0]           = v0;
                xl_out[(size_t)(j0 + 1) * RTOT + r0]     = v1;
                xl_out[(size_t)j0 * RTOT + r0 + 8]       = v2;
                xl_out[(size_t)(j0 + 1) * RTOT + r0 + 8] = v3;
            }
            float s0 = v0 + v2, s1 = v1 + v3;   // partial d-sum (2 rows)
            s0 += __shfl_xor_sync(0xffffffffu, s0, 4);
            s1 += __shfl_xor_sync(0xffffffffu, s1, 4);
            s0 += __shfl_xor_sync(0xffffffffu, s0, 8);
            s1 += __shfl_xor_sync(0xffffffffu, s1, 8);
            s0 += __shfl_xor_sync(0xffffffffu, s0, 16);
            s1 += __shfl_xor_sync(0xffffffffu, s1, 16);
            if (lane < 4) {
                float* dst = out + (size_t)batch * OUTW + LAYER * NOUT + ncol + nt * 8 + lane * 2;
                dst[0] = s0;
                dst[1] = s1;
            }
        }
    }
}

// ---------------- host ----------------
extern "C" void kernel_launch(void* const* d_in, const int* in_sizes, int n_in,
                              void* d_out, int out_size)
{
    const float* inputs = (const float*)d_in[0];
    const float* W0     = (const float*)d_in[1];
    const float* b0     = (const float*)d_in[2];
    const float* W1     = (const float*)d_in[3];
    const float* b1     = (const float*)d_in[4];
    const float* W2     = (const float*)d_in[5];
    const float* b2     = (const float*)d_in[6];
    float* out = (float*)d_out;

    cudaFuncSetAttribute(cin_mma<0>, cudaFuncAttributeMaxDynamicSharedMemorySize, SMEM_TOTAL);
    cudaFuncSetAttribute(cin_mma<1>, cudaFuncAttributeMaxDynamicSharedMemorySize, SMEM_TOTAL);
    cudaFuncSetAttribute(cin_mma<2>, cudaFuncAttributeMaxDynamicSharedMemorySize, SMEM_TOTAL);

    wprep<0><<<32,  NTHR>>>(W0);
    wprep<1><<<128, NTHR>>>(W1);
    wprep<2><<<128, NTHR>>>(W2);

    cin_mma<0><<<NCTA, NTHR, SMEM_TOTAL>>>(inputs, b0, out);
    cin_mma<1><<<NCTA, NTHR, SMEM_TOTAL>>>(inputs, b1, out);
    cin_mma<2><<<NCTA, NTHR, SMEM_TOTAL>>>(inputs, b2, out);
}